// round 10
// baseline (speedup 1.0000x reference)
#include <cuda_runtime.h>
#include <math.h>
#include <stdint.h>

// Problem constants
#define Bv   2
#define Sv   2048
#define Hv   2048
#define NHv  16
#define HDv  128
#define Iv   5632
#define Tv   (Bv * Sv)            // 4096 tokens
#define EPSv 1e-5f
#define SCALEv 0.08838834764831845f   // 1/sqrt(128)

// Smem row stride (words). 136 ≡ 8 (mod 32) makes fragment-read banks
// (8*tg + g) mod 32 a bijection over the warp -> conflict-free LDS.
#define LDS_STRIDE 136

// ---------------- scratch (static __device__: allocation-free) -------------
__device__ float g_xn[Tv * Hv];
__device__ float g_q[Tv * Hv];
__device__ float g_k[Tv * Hv];
__device__ float g_v[Tv * Hv];
__device__ float g_scores[(size_t)Bv * NHv * Sv * Sv];  // 536 MB
__device__ float g_ctx[Tv * Hv];
__device__ float g_hidden[Tv * Hv];
__device__ float g_y[Tv * Hv];
__device__ float g_fc1[Tv * 2 * Iv];
__device__ float g_act[Tv * Iv];

// ---------------- RMSNorm: one block per row of H=2048 --------------------
__global__ void rmsnorm_kernel(const float* __restrict__ x,
                               const float* __restrict__ w,
                               float* __restrict__ out) {
    int r = blockIdx.x;
    const float* xr = x + (size_t)r * Hv;
    float* orow = out + (size_t)r * Hv;
    float v[8];
    float ss = 0.f;
#pragma unroll
    for (int i = 0; i < 8; i++) {
        v[i] = xr[threadIdx.x + i * 256];
        ss += v[i] * v[i];
    }
    __shared__ float red[32];
    int lane = threadIdx.x & 31, wid = threadIdx.x >> 5;
#pragma unroll
    for (int o = 16; o > 0; o >>= 1) ss += __shfl_xor_sync(0xffffffffu, ss, o);
    if (lane == 0) red[wid] = ss;
    __syncthreads();
    if (wid == 0) {
        float t = (lane < 8) ? red[lane] : 0.f;
#pragma unroll
        for (int o = 4; o > 0; o >>= 1) t += __shfl_xor_sync(0xffffffffu, t, o);
        if (lane == 0) red[0] = rsqrtf(t * (1.0f / Hv) + EPSv);
    }
    __syncthreads();
    float rs = red[0];
#pragma unroll
    for (int i = 0; i < 8; i++) {
        int c = threadIdx.x + i * 256;
        orow[c] = v[i] * rs * w[c];
    }
}

// ---------------- Softmax over key dim (S=2048), with mask + scale --------
__global__ void softmax_kernel(float* __restrict__ sc,
                               const float* __restrict__ mask) {
    int r = blockIdx.x;                  // row in [0, B*NH*S)
    int b = r / (NHv * Sv);
    float* row = sc + (size_t)r * Sv;
    const float* mrow = mask + (size_t)b * Sv;

    float l[8];
    float mx = -1e30f;
#pragma unroll
    for (int i = 0; i < 8; i++) {
        int c = threadIdx.x + i * 256;
        float val = row[c] * SCALEv + (1.0f - mrow[c]) * -10000.0f;
        l[i] = val;
        mx = fmaxf(mx, val);
    }
    __shared__ float red[32];
    int lane = threadIdx.x & 31, wid = threadIdx.x >> 5;
#pragma unroll
    for (int o = 16; o > 0; o >>= 1) mx = fmaxf(mx, __shfl_xor_sync(0xffffffffu, mx, o));
    if (lane == 0) red[wid] = mx;
    __syncthreads();
    if (wid == 0) {
        float t = (lane < 8) ? red[lane] : -1e30f;
#pragma unroll
        for (int o = 4; o > 0; o >>= 1) t = fmaxf(t, __shfl_xor_sync(0xffffffffu, t, o));
        if (lane == 0) red[0] = t;
    }
    __syncthreads();
    mx = red[0];
    __syncthreads();

    float sum = 0.f;
#pragma unroll
    for (int i = 0; i < 8; i++) {
        float e = __expf(l[i] - mx);
        l[i] = e;
        sum += e;
    }
#pragma unroll
    for (int o = 16; o > 0; o >>= 1) sum += __shfl_xor_sync(0xffffffffu, sum, o);
    if (lane == 0) red[wid] = sum;
    __syncthreads();
    if (wid == 0) {
        float t = (lane < 8) ? red[lane] : 0.f;
#pragma unroll
        for (int o = 4; o > 0; o >>= 1) t += __shfl_xor_sync(0xffffffffu, t, o);
        if (lane == 0) red[0] = t;
    }
    __syncthreads();
    float inv = 1.0f / red[0];
#pragma unroll
    for (int i = 0; i < 8; i++) {
        int c = threadIdx.x + i * 256;
        row[c] = l[i] * inv;
    }
}

// ---------------- SwiGLU: act = silu(gate) * up (float4 vectorized) -------
__global__ void swiglu_kernel(const float* __restrict__ h,
                              float* __restrict__ act) {
    int idx = blockIdx.x * blockDim.x + threadIdx.x;   // in float4 units
    int total4 = Tv * Iv / 4;
    if (idx >= total4) return;
    int per_row4 = Iv / 4;
    int t = idx / per_row4, j4 = idx - t * per_row4;
    const float4* grow = (const float4*)(h + (size_t)t * (2 * Iv));
    float4 g = grow[j4];
    float4 u = grow[j4 + per_row4];
    float4 r;
    r.x = (g.x / (1.0f + __expf(-g.x))) * u.x;
    r.y = (g.y / (1.0f + __expf(-g.y))) * u.y;
    r.z = (g.z / (1.0f + __expf(-g.z))) * u.z;
    r.w = (g.w / (1.0f + __expf(-g.w))) * u.w;
    ((float4*)act)[idx] = r;
}

// ---------------- tf32 helpers --------------------------------------------
__device__ __forceinline__ uint32_t f2tf32(float x) {
    uint32_t r;
    asm("cvt.rna.tf32.f32 %0, %1;" : "=r"(r) : "f"(x));
    return r;
}

__device__ __forceinline__ void mma_tf32(float* d, const uint32_t* a, const uint32_t* b) {
    asm volatile(
        "mma.sync.aligned.m16n8k8.row.col.f32.tf32.tf32.f32 "
        "{%0,%1,%2,%3}, {%4,%5,%6,%7}, {%8,%9}, {%0,%1,%2,%3};\n"
        : "+f"(d[0]), "+f"(d[1]), "+f"(d[2]), "+f"(d[3])
        : "r"(a[0]), "r"(a[1]), "r"(a[2]), "r"(a[3]), "r"(b[0]), "r"(b[1]));
}

// ---------------- tf32 tensor-core GEMM: C = A * op(B) [+bias] [+resid] ---
// BM=BN=128, BK=16, 256 threads (8 warps), warp tile 64x32 via m16n8k8.
// Double-buffered smem; row stride LDS_STRIDE=136 (== 8 mod 32) makes both
// fragment reads and all staging writes bank-conflict-free.
// Requirements: M%128==0, N%128==0, K%16==0. Batched via blockIdx.z.
template <bool TRANSB>
__global__ __launch_bounds__(256, 2)
void tgemm_kernel(const float* __restrict__ A, const float* __restrict__ Bm,
                  const float* __restrict__ bias, const float* __restrict__ resid,
                  float* __restrict__ C,
                  int M, int N, int K, int lda, int ldb, int ldc,
                  int bInner,
                  long aIn, long aOut, long bIn, long bOut, long cIn, long cOut) {
    int z = blockIdx.z;
    int zi = z % bInner, zo = z / bInner;
    A += (long)zi * aIn + (long)zo * aOut;
    Bm += (long)zi * bIn + (long)zo * bOut;
    long coff = (long)zi * cIn + (long)zo * cOut;
    C += coff;
    if (resid) resid += coff;

    __shared__ uint32_t As[2][16][LDS_STRIDE];   // [buf][k][m]
    __shared__ uint32_t Bs[2][16][LDS_STRIDE];   // [buf][k][n]

    int tid = threadIdx.x;
    int lane = tid & 31;
    int warp = tid >> 5;
    int g = lane >> 2;        // 0..7
    int tg = lane & 3;        // 0..3
    int warp_m = warp & 1;    // 2 warps along M (64 each)
    int warp_n = warp >> 1;   // 4 warps along N (32 each)
    int m0 = blockIdx.y * 128, n0 = blockIdx.x * 128;

    // A loader: thread covers (row = tid&127, k = (tid>>7)*8 + 0..7)
    int aRow = tid & 127;
    int aKh = (tid >> 7) * 8;
    const float* Ap = A + (long)(m0 + aRow) * lda + aKh;

    // B loader
    const float* Bp;
    int bR, bC;
    long bStep;                // pointer increment per 16-k slab
    if (TRANSB) {             // B is [N,K]: transpose-load along k
        bR = tid & 127;       // n index
        bC = (tid >> 7) * 8;  // k offset
        Bp = Bm + (long)(n0 + bR) * ldb + bC;
        bStep = 16;
    } else {                  // B is [K,N]: direct rows
        bR = tid >> 4;        // k index 0..15
        bC = (tid & 15) * 4;  // n offset (two halves: +0, +64)
        Bp = Bm + (long)bR * ldb + n0 + bC;
        bStep = (long)16 * ldb;
    }

    float acc[4][4][4];
#pragma unroll
    for (int i = 0; i < 4; i++)
#pragma unroll
        for (int j = 0; j < 4; j++)
#pragma unroll
            for (int r = 0; r < 4; r++) acc[i][j][r] = 0.f;

    // ---- stage slab 0 into buffer 0 ----
    float4 av0 = *(const float4*)(Ap);
    float4 av1 = *(const float4*)(Ap + 4);
    float4 bv0, bv1;
    if (TRANSB) {
        bv0 = *(const float4*)(Bp);
        bv1 = *(const float4*)(Bp + 4);
    } else {
        bv0 = *(const float4*)(Bp);
        bv1 = *(const float4*)(Bp + 64);
    }
    As[0][aKh + 0][aRow] = f2tf32(av0.x);
    As[0][aKh + 1][aRow] = f2tf32(av0.y);
    As[0][aKh + 2][aRow] = f2tf32(av0.z);
    As[0][aKh + 3][aRow] = f2tf32(av0.w);
    As[0][aKh + 4][aRow] = f2tf32(av1.x);
    As[0][aKh + 5][aRow] = f2tf32(av1.y);
    As[0][aKh + 6][aRow] = f2tf32(av1.z);
    As[0][aKh + 7][aRow] = f2tf32(av1.w);
    if (TRANSB) {
        Bs[0][bC + 0][bR] = f2tf32(bv0.x);
        Bs[0][bC + 1][bR] = f2tf32(bv0.y);
        Bs[0][bC + 2][bR] = f2tf32(bv0.z);
        Bs[0][bC + 3][bR] = f2tf32(bv0.w);
        Bs[0][bC + 4][bR] = f2tf32(bv1.x);
        Bs[0][bC + 5][bR] = f2tf32(bv1.y);
        Bs[0][bC + 6][bR] = f2tf32(bv1.z);
        Bs[0][bC + 7][bR] = f2tf32(bv1.w);
    } else {
        uint4 p0 = make_uint4(f2tf32(bv0.x), f2tf32(bv0.y), f2tf32(bv0.z), f2tf32(bv0.w));
        uint4 p1 = make_uint4(f2tf32(bv1.x), f2tf32(bv1.y), f2tf32(bv1.z), f2tf32(bv1.w));
        *(uint4*)&Bs[0][bR][bC] = p0;
        *(uint4*)&Bs[0][bR][bC + 64] = p1;
    }
    __syncthreads();

    const float* ApNext = Ap + 16;
    const float* BpNext = Bp + bStep;
    int buf = 0;
    for (int kt = 0; kt < K; kt += 16) {
        bool has_next = (kt + 16 < K);
        // issue next slab's global loads FIRST (latency hides under MMAs)
        if (has_next) {
            av0 = *(const float4*)(ApNext);
            av1 = *(const float4*)(ApNext + 4);
            if (TRANSB) {
                bv0 = *(const float4*)(BpNext);
                bv1 = *(const float4*)(BpNext + 4);
            } else {
                bv0 = *(const float4*)(BpNext);
                bv1 = *(const float4*)(BpNext + 64);
            }
            ApNext += 16;
            BpNext += bStep;
        }

        // compute both kk halves from current buffer
#pragma unroll
        for (int kk = 0; kk < 16; kk += 8) {
            uint32_t af[4][4], bf[4][2];
#pragma unroll
            for (int im = 0; im < 4; im++) {
                int rowb = warp_m * 64 + im * 16 + g;
                af[im][0] = As[buf][kk + tg][rowb];
                af[im][1] = As[buf][kk + tg][rowb + 8];
                af[im][2] = As[buf][kk + tg + 4][rowb];
                af[im][3] = As[buf][kk + tg + 4][rowb + 8];
            }
#pragma unroll
            for (int jn = 0; jn < 4; jn++) {
                int colb = warp_n * 32 + jn * 8 + g;
                bf[jn][0] = Bs[buf][kk + tg][colb];
                bf[jn][1] = Bs[buf][kk + tg + 4][colb];
            }
#pragma unroll
            for (int im = 0; im < 4; im++)
#pragma unroll
                for (int jn = 0; jn < 4; jn++)
                    mma_tf32(acc[im][jn], af[im], bf[jn]);
        }

        // stage next slab into the other buffer
        if (has_next) {
            int nb = buf ^ 1;
            As[nb][aKh + 0][aRow] = f2tf32(av0.x);
            As[nb][aKh + 1][aRow] = f2tf32(av0.y);
            As[nb][aKh + 2][aRow] = f2tf32(av0.z);
            As[nb][aKh + 3][aRow] = f2tf32(av0.w);
            As[nb][aKh + 4][aRow] = f2tf32(av1.x);
            As[nb][aKh + 5][aRow] = f2tf32(av1.y);
            As[nb][aKh + 6][aRow] = f2tf32(av1.z);
            As[nb][aKh + 7][aRow] = f2tf32(av1.w);
            if (TRANSB) {
                Bs[nb][bC + 0][bR] = f2tf32(bv0.x);
                Bs[nb][bC + 1][bR] = f2tf32(bv0.y);
                Bs[nb][bC + 2][bR] = f2tf32(bv0.z);
                Bs[nb][bC + 3][bR] = f2tf32(bv0.w);
                Bs[nb][bC + 4][bR] = f2tf32(bv1.x);
                Bs[nb][bC + 5][bR] = f2tf32(bv1.y);
                Bs[nb][bC + 6][bR] = f2tf32(bv1.z);
                Bs[nb][bC + 7][bR] = f2tf32(bv1.w);
            } else {
                uint4 p0 = make_uint4(f2tf32(bv0.x), f2tf32(bv0.y), f2tf32(bv0.z), f2tf32(bv0.w));
                uint4 p1 = make_uint4(f2tf32(bv1.x), f2tf32(bv1.y), f2tf32(bv1.z), f2tf32(bv1.w));
                *(uint4*)&Bs[nb][bR][bC] = p0;
                *(uint4*)&Bs[nb][bR][bC + 64] = p1;
            }
            __syncthreads();
            buf = nb;
        }
    }

    // Epilogue: fragment layout c0,c1 at (row, col..col+1), c2,c3 at (row+8)
#pragma unroll
    for (int im = 0; im < 4; im++) {
#pragma unroll
        for (int jn = 0; jn < 4; jn++) {
            int r0 = m0 + warp_m * 64 + im * 16 + g;
            int c0 = n0 + warp_n * 32 + jn * 8 + tg * 2;
            float2 bb = make_float2(0.f, 0.f);
            if (bias) bb = *(const float2*)(bias + c0);
            float2 o0 = make_float2(acc[im][jn][0] + bb.x, acc[im][jn][1] + bb.y);
            float2 o1 = make_float2(acc[im][jn][2] + bb.x, acc[im][jn][3] + bb.y);
            if (resid) {
                float2 rr0 = *(const float2*)(resid + (long)r0 * ldc + c0);
                float2 rr1 = *(const float2*)(resid + (long)(r0 + 8) * ldc + c0);
                o0.x += rr0.x; o0.y += rr0.y;
                o1.x += rr1.x; o1.y += rr1.y;
            }
            *(float2*)(C + (long)r0 * ldc + c0) = o0;
            *(float2*)(C + (long)(r0 + 8) * ldc + c0) = o1;
        }
    }
}

// ---------------- launcher -------------------------------------------------
extern "C" void kernel_launch(void* const* d_in, const int* in_sizes, int n_in,
                              void* d_out, int out_size) {
    (void)in_sizes; (void)n_in; (void)out_size;
    const float* hs        = (const float*)d_in[0];
    const float* mask      = (const float*)d_in[1];
    const float* q_w       = (const float*)d_in[2];
    const float* q_b       = (const float*)d_in[3];
    const float* k_w       = (const float*)d_in[4];
    const float* k_b       = (const float*)d_in[5];
    const float* v_w       = (const float*)d_in[6];
    const float* v_b       = (const float*)d_in[7];
    const float* o_w       = (const float*)d_in[8];
    const float* o_b       = (const float*)d_in[9];
    const float* fc1_w     = (const float*)d_in[10];
    const float* fc1_b     = (const float*)d_in[11];
    const float* fc2_w     = (const float*)d_in[12];
    const float* fc2_b     = (const float*)d_in[13];
    const float* in_norm_w = (const float*)d_in[14];
    const float* post_norm_w = (const float*)d_in[15];
    float* out = (float*)d_out;

    float *xn, *q, *k, *v, *sc, *ctx, *hid, *y, *fc1, *act;
    cudaGetSymbolAddress((void**)&xn,  g_xn);
    cudaGetSymbolAddress((void**)&q,   g_q);
    cudaGetSymbolAddress((void**)&k,   g_k);
    cudaGetSymbolAddress((void**)&v,   g_v);
    cudaGetSymbolAddress((void**)&sc,  g_scores);
    cudaGetSymbolAddress((void**)&ctx, g_ctx);
    cudaGetSymbolAddress((void**)&hid, g_hidden);
    cudaGetSymbolAddress((void**)&y,   g_y);
    cudaGetSymbolAddress((void**)&fc1, g_fc1);
    cudaGetSymbolAddress((void**)&act, g_act);

    // 1. input RMSNorm
    rmsnorm_kernel<<<Tv, 256>>>(hs, in_norm_w, xn);

    // 2. Q/K/V projections: [T,H] x [H,H]
    dim3 gProj(Hv / 128, Tv / 128, 1);
    tgemm_kernel<false><<<gProj, 256>>>(xn, q_w, q_b, nullptr, q,
        Tv, Hv, Hv, Hv, Hv, Hv, 1, 0, 0, 0, 0, 0, 0);
    tgemm_kernel<false><<<gProj, 256>>>(xn, k_w, k_b, nullptr, k,
        Tv, Hv, Hv, Hv, Hv, Hv, 1, 0, 0, 0, 0, 0, 0);
    tgemm_kernel<false><<<gProj, 256>>>(xn, v_w, v_b, nullptr, v,
        Tv, Hv, Hv, Hv, Hv, Hv, 1, 0, 0, 0, 0, 0, 0);

    // 3. scores[b,h] = Q_bh @ K_bh^T   (batched over 32 heads)
    dim3 gSc(Sv / 128, Sv / 128, Bv * NHv);
    tgemm_kernel<true><<<gSc, 256>>>(q, k, nullptr, nullptr, sc,
        Sv, Sv, HDv, Hv, Hv, Sv, NHv,
        HDv, (long)Sv * Hv, HDv, (long)Sv * Hv,
        (long)Sv * Sv, (long)NHv * Sv * Sv);

    // 4. softmax with mask + scale
    softmax_kernel<<<Bv * NHv * Sv, 256>>>(sc, mask);

    // 5. ctx[b,h] = P_bh @ V_bh
    dim3 gCtx(HDv / 128, Sv / 128, Bv * NHv);
    tgemm_kernel<false><<<gCtx, 256>>>(sc, v, nullptr, nullptr, ctx,
        Sv, HDv, Sv, Sv, Hv, Hv, NHv,
        (long)Sv * Sv, (long)NHv * Sv * Sv,
        HDv, (long)Sv * Hv, HDv, (long)Sv * Hv);

    // 6. O projection + residual -> hidden
    tgemm_kernel<false><<<gProj, 256>>>(ctx, o_w, o_b, hs, hid,
        Tv, Hv, Hv, Hv, Hv, Hv, 1, 0, 0, 0, 0, 0, 0);

    // 7. post RMSNorm
    rmsnorm_kernel<<<Tv, 256>>>(hid, post_norm_w, y);

    // 8. FC1: [T,H] x [H,2I]
    dim3 gFc1((2 * Iv) / 128, Tv / 128, 1);
    tgemm_kernel<false><<<gFc1, 256>>>(y, fc1_w, fc1_b, nullptr, fc1,
        Tv, 2 * Iv, Hv, Hv, 2 * Iv, 2 * Iv, 1, 0, 0, 0, 0, 0, 0);

    // 9. SwiGLU (float4)
    swiglu_kernel<<<(Tv * Iv / 4 + 255) / 256, 256>>>(fc1, act);

    // 10. FC2 + residual -> out
    tgemm_kernel<false><<<gProj, 256>>>(act, fc2_w, fc2_b, hid, out,
        Tv, Hv, Iv, Iv, Hv, Hv, 1, 0, 0, 0, 0, 0, 0);
}

// round 12
// speedup vs baseline: 1.2850x; 1.2850x over previous
#include <cuda_runtime.h>
#include <math.h>
#include <stdint.h>

// Problem constants
#define Bv   2
#define Sv   2048
#define Hv   2048
#define NHv  16
#define HDv  128
#define Iv   5632
#define Tv   (Bv * Sv)            // 4096 tokens
#define EPSv 1e-5f
#define SCALEv 0.08838834764831845f   // 1/sqrt(128)

// Smem strides (words). 136 ≡ 8, 20 ≡ 20 (mod 32): both make the fragment
// read bank index a bijection over the 32 lanes -> conflict-free.
#define STRIDE_KN 136    // [k][n] layout rows (B, non-transposed)
#define STRIDE_MK 20     // [m][k] layout rows (A, and B when TRANSB)
#define BUF_WORDS 2560   // per-buffer flat size (128*20 = 2560 >= 16*136 = 2176)

// ---------------- scratch (static __device__: allocation-free) -------------
__device__ float g_xn[Tv * Hv];
__device__ float g_q[Tv * Hv];
__device__ float g_k[Tv * Hv];
__device__ float g_v[Tv * Hv];
__device__ float g_scores[(size_t)Bv * NHv * Sv * Sv];  // 536 MB
__device__ float g_ctx[Tv * Hv];
__device__ float g_hidden[Tv * Hv];
__device__ float g_y[Tv * Hv];
__device__ float g_fc1[Tv * 2 * Iv];
__device__ float g_act[Tv * Iv];
// tf32-pre-rounded weights
__device__ float g_qw[Hv * Hv];
__device__ float g_kw[Hv * Hv];
__device__ float g_vw[Hv * Hv];
__device__ float g_ow[Hv * Hv];
__device__ float g_fc1w[Hv * 2 * Iv];
__device__ float g_fc2w[Iv * Hv];

// ---------------- tf32 helpers --------------------------------------------
__device__ __forceinline__ float tf32r(float x) {
    uint32_t u;
    asm("cvt.rna.tf32.f32 %0, %1;" : "=r"(u) : "f"(x));
    return __uint_as_float(u);
}

__device__ __forceinline__ void mma_tf32(float* d, const uint32_t* a, const uint32_t* b) {
    asm volatile(
        "mma.sync.aligned.m16n8k8.row.col.f32.tf32.tf32.f32 "
        "{%0,%1,%2,%3}, {%4,%5,%6,%7}, {%8,%9}, {%0,%1,%2,%3};\n"
        : "+f"(d[0]), "+f"(d[1]), "+f"(d[2]), "+f"(d[3])
        : "r"(a[0]), "r"(a[1]), "r"(a[2]), "r"(a[3]), "r"(b[0]), "r"(b[1]));
}

#define CP_ASYNC16(dst_u32, src_ptr) \
    asm volatile("cp.async.cg.shared.global [%0], [%1], 16;" :: "r"(dst_u32), "l"(src_ptr))
#define CP_COMMIT() asm volatile("cp.async.commit_group;" ::: "memory")
#define CP_WAIT0()  asm volatile("cp.async.wait_group 0;" ::: "memory")

// ---------------- weight pre-rounding: out[i] = tf32(in[i]) ---------------
__global__ void cvt_tf32_kernel(const float* __restrict__ in,
                                float* __restrict__ out, int n4) {
    int i = blockIdx.x * blockDim.x + threadIdx.x;
    if (i >= n4) return;
    float4 v = ((const float4*)in)[i];
    v.x = tf32r(v.x); v.y = tf32r(v.y); v.z = tf32r(v.z); v.w = tf32r(v.w);
    ((float4*)out)[i] = v;
}

// ---------------- RMSNorm: one block per row; output tf32-rounded ---------
__global__ void rmsnorm_kernel(const float* __restrict__ x,
                               const float* __restrict__ w,
                               float* __restrict__ out) {
    int r = blockIdx.x;
    const float* xr = x + (size_t)r * Hv;
    float* orow = out + (size_t)r * Hv;
    float v[8];
    float ss = 0.f;
#pragma unroll
    for (int i = 0; i < 8; i++) {
        v[i] = xr[threadIdx.x + i * 256];
        ss += v[i] * v[i];
    }
    __shared__ float red[32];
    int lane = threadIdx.x & 31, wid = threadIdx.x >> 5;
#pragma unroll
    for (int o = 16; o > 0; o >>= 1) ss += __shfl_xor_sync(0xffffffffu, ss, o);
    if (lane == 0) red[wid] = ss;
    __syncthreads();
    if (wid == 0) {
        float t = (lane < 8) ? red[lane] : 0.f;
#pragma unroll
        for (int o = 4; o > 0; o >>= 1) t += __shfl_xor_sync(0xffffffffu, t, o);
        if (lane == 0) red[0] = rsqrtf(t * (1.0f / Hv) + EPSv);
    }
    __syncthreads();
    float rs = red[0];
#pragma unroll
    for (int i = 0; i < 8; i++) {
        int c = threadIdx.x + i * 256;
        orow[c] = tf32r(v[i] * rs * w[c]);
    }
}

// ---------------- Softmax (mask+scale); output tf32-rounded ---------------
__global__ void softmax_kernel(float* __restrict__ sc,
                               const float* __restrict__ mask) {
    int r = blockIdx.x;
    int b = r / (NHv * Sv);
    float* row = sc + (size_t)r * Sv;
    const float* mrow = mask + (size_t)b * Sv;

    float l[8];
    float mx = -1e30f;
#pragma unroll
    for (int i = 0; i < 8; i++) {
        int c = threadIdx.x + i * 256;
        float val = row[c] * SCALEv + (1.0f - mrow[c]) * -10000.0f;
        l[i] = val;
        mx = fmaxf(mx, val);
    }
    __shared__ float red[32];
    int lane = threadIdx.x & 31, wid = threadIdx.x >> 5;
#pragma unroll
    for (int o = 16; o > 0; o >>= 1) mx = fmaxf(mx, __shfl_xor_sync(0xffffffffu, mx, o));
    if (lane == 0) red[wid] = mx;
    __syncthreads();
    if (wid == 0) {
        float t = (lane < 8) ? red[lane] : -1e30f;
#pragma unroll
        for (int o = 4; o > 0; o >>= 1) t = fmaxf(t, __shfl_xor_sync(0xffffffffu, t, o));
        if (lane == 0) red[0] = t;
    }
    __syncthreads();
    mx = red[0];
    __syncthreads();

    float sum = 0.f;
#pragma unroll
    for (int i = 0; i < 8; i++) {
        float e = __expf(l[i] - mx);
        l[i] = e;
        sum += e;
    }
#pragma unroll
    for (int o = 16; o > 0; o >>= 1) sum += __shfl_xor_sync(0xffffffffu, sum, o);
    if (lane == 0) red[wid] = sum;
    __syncthreads();
    if (wid == 0) {
        float t = (lane < 8) ? red[lane] : 0.f;
#pragma unroll
        for (int o = 4; o > 0; o >>= 1) t += __shfl_xor_sync(0xffffffffu, t, o);
        if (lane == 0) red[0] = t;
    }
    __syncthreads();
    float inv = 1.0f / red[0];
#pragma unroll
    for (int i = 0; i < 8; i++) {
        int c = threadIdx.x + i * 256;
        row[c] = tf32r(l[i] * inv);
    }
}

// ---------------- SwiGLU; output tf32-rounded -----------------------------
__global__ void swiglu_kernel(const float* __restrict__ h,
                              float* __restrict__ act) {
    int idx = blockIdx.x * blockDim.x + threadIdx.x;
    int total4 = Tv * Iv / 4;
    if (idx >= total4) return;
    int per_row4 = Iv / 4;
    int t = idx / per_row4, j4 = idx - t * per_row4;
    const float4* grow = (const float4*)(h + (size_t)t * (2 * Iv));
    float4 g = grow[j4];
    float4 u = grow[j4 + per_row4];
    float4 r;
    r.x = tf32r((g.x / (1.0f + __expf(-g.x))) * u.x);
    r.y = tf32r((g.y / (1.0f + __expf(-g.y))) * u.y);
    r.z = tf32r((g.z / (1.0f + __expf(-g.z))) * u.z);
    r.w = tf32r((g.w / (1.0f + __expf(-g.w))) * u.w);
    ((float4*)act)[idx] = r;
}

// ---------------- tf32 tensor-core GEMM (cp.async staging) ----------------
// Inputs MUST already be tf32-rounded (low 13 mantissa bits zero) — the MMA
// consumes raw bits. BM=BN=128, BK=16, 256 threads, warp tile 64x32.
// A staged as [m][k] stride 20 (direct 16B cp.async; reads conflict-free).
// B: TRANSB -> [n][k] stride 20 (direct cp.async); else [k][n] stride 136.
// Double-buffered; one cp.async group + one __syncthreads per slab.
template <bool TRANSB>
__global__ __launch_bounds__(256, 2)
void tgemm_kernel(const float* __restrict__ A, const float* __restrict__ Bm,
                  const float* __restrict__ bias, const float* __restrict__ resid,
                  float* __restrict__ C,
                  int M, int N, int K, int lda, int ldb, int ldc,
                  int bInner, int roundC,
                  long aIn, long aOut, long bIn, long bOut, long cIn, long cOut) {
    int z = blockIdx.z;
    int zi = z % bInner, zo = z / bInner;
    A += (long)zi * aIn + (long)zo * aOut;
    Bm += (long)zi * bIn + (long)zo * bOut;
    long coff = (long)zi * cIn + (long)zo * cOut;
    C += coff;
    if (resid) resid += coff;

    __shared__ uint32_t AsF[2 * BUF_WORDS];
    __shared__ uint32_t BsF[2 * BUF_WORDS];

    int tid = threadIdx.x;
    int lane = tid & 31;
    int warp = tid >> 5;
    int g = lane >> 2;        // 0..7
    int tg = lane & 3;        // 0..3
    int warp_m = warp & 1;    // 2 warps along M (64 each)
    int warp_n = warp >> 1;   // 4 warps along N (32 each)
    int m0 = blockIdx.y * 128, n0 = blockIdx.x * 128;

    uint32_t sA = (uint32_t)__cvta_generic_to_shared(AsF);
    uint32_t sB = (uint32_t)__cvta_generic_to_shared(BsF);

    // A staging: row = tid>>1 (0..127), k-offset = (tid&1)*8 (+0,+4)
    int aRow = tid >> 1;
    int aC = (tid & 1) * 8;
    const float* Ap = A + (long)(m0 + aRow) * lda + aC;
    uint32_t aDst = (uint32_t)(aRow * STRIDE_MK + aC) * 4u;

    // B staging
    const float* Bp;
    uint32_t bDst0, bDst1;
    long bStep;
    if (TRANSB) {             // B[N,K]: row = n, direct copy into [n][k]@20
        int bN = tid >> 1;
        int bC = (tid & 1) * 8;
        Bp = Bm + (long)(n0 + bN) * ldb + bC;
        bDst0 = (uint32_t)(bN * STRIDE_MK + bC) * 4u;
        bDst1 = bDst0 + 16u;
        bStep = 16;
    } else {                  // B[K,N]: row = k, into [k][n]@136
        int bR = tid >> 4;    // 0..15
        int bC = (tid & 15) * 8;
        Bp = Bm + (long)bR * ldb + n0 + bC;
        bDst0 = (uint32_t)(bR * STRIDE_KN + bC) * 4u;
        bDst1 = bDst0 + 16u;
        bStep = (long)16 * ldb;
    }
    uint32_t aDst1 = aDst + 16u;

    float acc[4][4][4];
#pragma unroll
    for (int i = 0; i < 4; i++)
#pragma unroll
        for (int j = 0; j < 4; j++)
#pragma unroll
            for (int r = 0; r < 4; r++) acc[i][j][r] = 0.f;

    // ---- stage slab 0 into buffer 0 ----
    CP_ASYNC16(sA + aDst, Ap);
    CP_ASYNC16(sA + aDst1, Ap + 4);
    CP_ASYNC16(sB + bDst0, Bp);
    CP_ASYNC16(sB + bDst1, Bp + 4);
    CP_COMMIT();
    CP_WAIT0();
    __syncthreads();

    const float* ApNext = Ap + 16;
    const float* BpNext = Bp + bStep;
    int buf = 0;
    const uint32_t bufBytes = BUF_WORDS * 4u;

    for (int kt = 0; kt < K; kt += 16) {
        bool has_next = (kt + 16 < K);
        if (has_next) {
            uint32_t off = (buf ^ 1) ? bufBytes : 0u;
            CP_ASYNC16(sA + off + aDst, ApNext);
            CP_ASYNC16(sA + off + aDst1, ApNext + 4);
            CP_ASYNC16(sB + off + bDst0, BpNext);
            CP_ASYNC16(sB + off + bDst1, BpNext + 4);
            CP_COMMIT();
            ApNext += 16;
            BpNext += bStep;
        }

        const uint32_t* Ab = AsF + buf * BUF_WORDS;
        const uint32_t* Bb = BsF + buf * BUF_WORDS;
#pragma unroll
        for (int kk = 0; kk < 16; kk += 8) {
            uint32_t af[4][4], bf[4][2];
#pragma unroll
            for (int im = 0; im < 4; im++) {
                int rowb = warp_m * 64 + im * 16 + g;
                af[im][0] = Ab[rowb * STRIDE_MK + kk + tg];
                af[im][1] = Ab[(rowb + 8) * STRIDE_MK + kk + tg];
                af[im][2] = Ab[rowb * STRIDE_MK + kk + tg + 4];
                af[im][3] = Ab[(rowb + 8) * STRIDE_MK + kk + tg + 4];
            }
#pragma unroll
            for (int jn = 0; jn < 4; jn++) {
                int colb = warp_n * 32 + jn * 8 + g;
                if (TRANSB) {
                    bf[jn][0] = Bb[colb * STRIDE_MK + kk + tg];
                    bf[jn][1] = Bb[colb * STRIDE_MK + kk + tg + 4];
                } else {
                    bf[jn][0] = Bb[(kk + tg) * STRIDE_KN + colb];
                    bf[jn][1] = Bb[(kk + tg + 4) * STRIDE_KN + colb];
                }
            }
#pragma unroll
            for (int im = 0; im < 4; im++)
#pragma unroll
                for (int jn = 0; jn < 4; jn++)
                    mma_tf32(acc[im][jn], af[im], bf[jn]);
        }

        if (has_next) {
            CP_WAIT0();
            __syncthreads();
            buf ^= 1;
        }
    }

    // Epilogue
#pragma unroll
    for (int im = 0; im < 4; im++) {
#pragma unroll
        for (int jn = 0; jn < 4; jn++) {
            int r0 = m0 + warp_m * 64 + im * 16 + g;
            int c0 = n0 + warp_n * 32 + jn * 8 + tg * 2;
            float2 bb = make_float2(0.f, 0.f);
            if (bias) bb = *(const float2*)(bias + c0);
            float2 o0 = make_float2(acc[im][jn][0] + bb.x, acc[im][jn][1] + bb.y);
            float2 o1 = make_float2(acc[im][jn][2] + bb.x, acc[im][jn][3] + bb.y);
            if (resid) {
                float2 rr0 = *(const float2*)(resid + (long)r0 * ldc + c0);
                float2 rr1 = *(const float2*)(resid + (long)(r0 + 8) * ldc + c0);
                o0.x += rr0.x; o0.y += rr0.y;
                o1.x += rr1.x; o1.y += rr1.y;
            }
            if (roundC) {
                o0.x = tf32r(o0.x); o0.y = tf32r(o0.y);
                o1.x = tf32r(o1.x); o1.y = tf32r(o1.y);
            }
            *(float2*)(C + (long)r0 * ldc + c0) = o0;
            *(float2*)(C + (long)(r0 + 8) * ldc + c0) = o1;
        }
    }
}

// ---------------- launcher -------------------------------------------------
extern "C" void kernel_launch(void* const* d_in, const int* in_sizes, int n_in,
                              void* d_out, int out_size) {
    (void)in_sizes; (void)n_in; (void)out_size;
    const float* hs        = (const float*)d_in[0];
    const float* mask      = (const float*)d_in[1];
    const float* q_w       = (const float*)d_in[2];
    const float* q_b       = (const float*)d_in[3];
    const float* k_w       = (const float*)d_in[4];
    const float* k_b       = (const float*)d_in[5];
    const float* v_w       = (const float*)d_in[6];
    const float* v_b       = (const float*)d_in[7];
    const float* o_w       = (const float*)d_in[8];
    const float* o_b       = (const float*)d_in[9];
    const float* fc1_w     = (const float*)d_in[10];
    const float* fc1_b     = (const float*)d_in[11];
    const float* fc2_w     = (const float*)d_in[12];
    const float* fc2_b     = (const float*)d_in[13];
    const float* in_norm_w = (const float*)d_in[14];
    const float* post_norm_w = (const float*)d_in[15];
    float* out = (float*)d_out;

    float *xn, *q, *k, *v, *sc, *ctx, *hid, *y, *fc1, *act;
    float *qw, *kw, *vw, *ow, *fc1w, *fc2w;
    cudaGetSymbolAddress((void**)&xn,  g_xn);
    cudaGetSymbolAddress((void**)&q,   g_q);
    cudaGetSymbolAddress((void**)&k,   g_k);
    cudaGetSymbolAddress((void**)&v,   g_v);
    cudaGetSymbolAddress((void**)&sc,  g_scores);
    cudaGetSymbolAddress((void**)&ctx, g_ctx);
    cudaGetSymbolAddress((void**)&hid, g_hidden);
    cudaGetSymbolAddress((void**)&y,   g_y);
    cudaGetSymbolAddress((void**)&fc1, g_fc1);
    cudaGetSymbolAddress((void**)&act, g_act);
    cudaGetSymbolAddress((void**)&qw,  g_qw);
    cudaGetSymbolAddress((void**)&kw,  g_kw);
    cudaGetSymbolAddress((void**)&vw,  g_vw);
    cudaGetSymbolAddress((void**)&ow,  g_ow);
    cudaGetSymbolAddress((void**)&fc1w, g_fc1w);
    cudaGetSymbolAddress((void**)&fc2w, g_fc2w);

    // 0. pre-round weights to tf32
    int nW = Hv * Hv / 4;
    cvt_tf32_kernel<<<(nW + 255) / 256, 256>>>(q_w, qw, nW);
    cvt_tf32_kernel<<<(nW + 255) / 256, 256>>>(k_w, kw, nW);
    cvt_tf32_kernel<<<(nW + 255) / 256, 256>>>(v_w, vw, nW);
    cvt_tf32_kernel<<<(nW + 255) / 256, 256>>>(o_w, ow, nW);
    int nF1 = Hv * 2 * Iv / 4;
    cvt_tf32_kernel<<<(nF1 + 255) / 256, 256>>>(fc1_w, fc1w, nF1);
    int nF2 = Iv * Hv / 4;
    cvt_tf32_kernel<<<(nF2 + 255) / 256, 256>>>(fc2_w, fc2w, nF2);

    // 1. input RMSNorm (rounded)
    rmsnorm_kernel<<<Tv, 256>>>(hs, in_norm_w, xn);

    // 2. Q/K/V projections (outputs rounded: feed scores/ctx GEMMs)
    dim3 gProj(Hv / 128, Tv / 128, 1);
    tgemm_kernel<false><<<gProj, 256>>>(xn, qw, q_b, nullptr, q,
        Tv, Hv, Hv, Hv, Hv, Hv, 1, 1, 0, 0, 0, 0, 0, 0);
    tgemm_kernel<false><<<gProj, 256>>>(xn, kw, k_b, nullptr, k,
        Tv, Hv, Hv, Hv, Hv, Hv, 1, 1, 0, 0, 0, 0, 0, 0);
    tgemm_kernel<false><<<gProj, 256>>>(xn, vw, v_b, nullptr, v,
        Tv, Hv, Hv, Hv, Hv, Hv, 1, 1, 0, 0, 0, 0, 0, 0);

    // 3. scores = Q @ K^T (batched over 32 heads); softmax rounds after
    dim3 gSc(Sv / 128, Sv / 128, Bv * NHv);
    tgemm_kernel<true><<<gSc, 256>>>(q, k, nullptr, nullptr, sc,
        Sv, Sv, HDv, Hv, Hv, Sv, NHv, 0,
        HDv, (long)Sv * Hv, HDv, (long)Sv * Hv,
        (long)Sv * Sv, (long)NHv * Sv * Sv);

    // 4. softmax (rounded output)
    softmax_kernel<<<Bv * NHv * Sv, 256>>>(sc, mask);

    // 5. ctx = P @ V (rounded: feeds O-proj)
    dim3 gCtx(HDv / 128, Sv / 128, Bv * NHv);
    tgemm_kernel<false><<<gCtx, 256>>>(sc, v, nullptr, nullptr, ctx,
        Sv, HDv, Sv, Sv, Hv, Hv, NHv, 1,
        (long)Sv * Sv, (long)NHv * Sv * Sv,
        HDv, (long)Sv * Hv, HDv, (long)Sv * Hv);

    // 6. O projection + residual -> hidden (NOT rounded: residual path)
    tgemm_kernel<false><<<gProj, 256>>>(ctx, ow, o_b, hs, hid,
        Tv, Hv, Hv, Hv, Hv, Hv, 1, 0, 0, 0, 0, 0, 0, 0);

    // 7. post RMSNorm (rounded)
    rmsnorm_kernel<<<Tv, 256>>>(hid, post_norm_w, y);

    // 8. FC1 (swiglu rounds after)
    dim3 gFc1((2 * Iv) / 128, Tv / 128, 1);
    tgemm_kernel<false><<<gFc1, 256>>>(y, fc1w, fc1_b, nullptr, fc1,
        Tv, 2 * Iv, Hv, Hv, 2 * Iv, 2 * Iv, 1, 0, 0, 0, 0, 0, 0, 0);

    // 9. SwiGLU (rounded)
    swiglu_kernel<<<(Tv * Iv / 4 + 255) / 256, 256>>>(fc1, act);

    // 10. FC2 + residual -> out (NOT rounded: final output)
    tgemm_kernel<false><<<gProj, 256>>>(act, fc2w, fc2_b, hid, out,
        Tv, Hv, Iv, Iv, Hv, Hv, 1, 0, 0, 0, 0, 0, 0, 0);
}